// round 9
// baseline (speedup 1.0000x reference)
#include <cuda_runtime.h>
#include <cstdint>

// out[m][d] = sum_k ecg[m*128+k] * W[d*128+k] + b[d],  M=196608, K=128, N=64.
// bf16-split HMMA: D = Ahi*Whi + Alo*Whi + Ahi*Wlo.
// This revision: term-major MMA issue order (same-acc RAW distance 4) and a
// rolling double-buffer on W ldsm fragments (prefetch iter i+1 before MMAs of i).

#define THREADS 128
#define BM 128
#define WPAD 136   // bf16 per padded W row (272 B rows -> conflict-free ldmatrix)

__device__ __forceinline__ uint32_t s2u(const void* p) {
    uint32_t a;
    asm("{ .reg .u64 t; cvta.to.shared.u64 t, %1; cvt.u32.u64 %0, t; }" : "=r"(a) : "l"(p));
    return a;
}

__device__ __forceinline__ void split2(float x, float y, uint32_t& hi, uint32_t& lo) {
    asm("cvt.rn.bf16x2.f32 %0, %1, %2;" : "=r"(hi) : "f"(y), "f"(x));
    float hx = __uint_as_float(hi << 16);
    float hy = __uint_as_float(hi & 0xffff0000u);
    float lx = x - hx, ly = y - hy;
    asm("cvt.rn.bf16x2.f32 %0, %1, %2;" : "=r"(lo) : "f"(ly), "f"(lx));
}

__device__ __forceinline__ void ldsm4(uint32_t* r, uint32_t addr) {
    asm volatile("ldmatrix.sync.aligned.m8n8.x4.shared.b16 {%0,%1,%2,%3}, [%4];"
                 : "=r"(r[0]), "=r"(r[1]), "=r"(r[2]), "=r"(r[3]) : "r"(addr));
}

__device__ __forceinline__ void mma16816(float* c,
                                         uint32_t a0, uint32_t a1, uint32_t a2, uint32_t a3,
                                         uint32_t b0, uint32_t b1) {
    asm volatile(
        "mma.sync.aligned.m16n8k16.row.col.f32.bf16.bf16.f32 "
        "{%0,%1,%2,%3}, {%4,%5,%6,%7}, {%8,%9}, {%0,%1,%2,%3};"
        : "+f"(c[0]), "+f"(c[1]), "+f"(c[2]), "+f"(c[3])
        : "r"(a0), "r"(a1), "r"(a2), "r"(a3), "r"(b0), "r"(b1));
}

__global__ __launch_bounds__(THREADS, 3)
void ecg_tok_mma(const float* __restrict__ ecg,
                 const float* __restrict__ W,
                 const float* __restrict__ bias,
                 float* __restrict__ out,
                 long long xelems, int fillCount) {
    __shared__ __align__(16) uint32_t Whi32[64 * WPAD / 2];
    __shared__ __align__(16) uint32_t Wlo32[64 * WPAD / 2];

    const int tid  = threadIdx.x;
    const int warp = tid >> 5;
    const int lane = tid & 31;
    const long long m0 = (long long)blockIdx.x * BM;

    // ---- folded fill: beat_intervals tail ----
    {
        int fi = blockIdx.x * THREADS + tid;
        if (fi < fillCount) out[xelems + fi] = 128.0f;
    }

    // ---- prologue: load + split W with per-16-chunk column permutation ----
    // global pair g of a chunk -> slice pair (g>>1) + (g&1)*4 (same perm on A).
    #pragma unroll
    for (int it = 0; it < 16; it++) {
        int idx   = tid + it * THREADS;     // 0..2047
        int n     = idx >> 5;
        int r     = idx & 31;
        int chunk = r >> 2;
        int q     = r & 3;
        float4 v = *reinterpret_cast<const float4*>(W + n * 128 + chunk * 16 + q * 4);
        uint32_t h0, l0, h1, l1;
        split2(v.x, v.y, h0, l0);
        split2(v.z, v.w, h1, l1);
        int u = n * (WPAD / 2) + chunk * 8 + q;
        Whi32[u]     = h0;
        Whi32[u + 4] = h1;
        Wlo32[u]     = l0;
        Wlo32[u + 4] = l1;
    }
    __syncthreads();

    // ldmatrix lane addressing
    const int lm_row  = ((lane >> 4) << 3) + (lane & 7);
    const int lm_kofs = ((lane >> 3) & 1) << 4;   // bytes
    const uint32_t lm_term  = (uint32_t)(lm_row * (WPAD * 2) + lm_kofs);
    const uint32_t whi_base = s2u(Whi32) + lm_term;
    const uint32_t wlo_base = s2u(Wlo32) + lm_term;

    // A geometry: warp rows = warp*32 + {0..31}; lane float4 at col 4*(lane&3)
    const int arow = warp * 32 + (lane >> 2);
    const float* abase = ecg + (m0 + arow) * 128 + 4 * (lane & 3);

    float acc[2][8][4];
    #pragma unroll
    for (int f = 0; f < 2; f++)
        #pragma unroll
        for (int nt = 0; nt < 8; nt++)
            #pragma unroll
            for (int j = 0; j < 4; j++) acc[f][nt][j] = 0.0f;

    // A prefetch (1-deep): cur holds k-step s
    float4 cur[4];
    #pragma unroll
    for (int j = 0; j < 4; j++)
        cur[j] = *reinterpret_cast<const float4*>(abase + j * 8 * 128);

    // W fragment rolling double-buffer over flattened (s, ntp) iterations
    uint32_t bh[2][4], bl[2][4];
    ldsm4(bh[0], whi_base);            // iter 0: s=0, ntp=0, off=0
    ldsm4(bl[0], wlo_base);

    #pragma unroll
    for (int s = 0; s < 8; s++) {
        // split current A chunk into fragments
        uint32_t ah[8], al[8];
        #pragma unroll
        for (int j = 0; j < 4; j++) {
            split2(cur[j].x, cur[j].y, ah[2 * j],     al[2 * j]);
            split2(cur[j].z, cur[j].w, ah[2 * j + 1], al[2 * j + 1]);
        }

        // prefetch next A chunk
        if (s < 7) {
            #pragma unroll
            for (int j = 0; j < 4; j++)
                cur[j] = *reinterpret_cast<const float4*>(
                    abase + (s + 1) * 16 + j * 8 * 128);
        }

        #pragma unroll
        for (int ntp = 0; ntp < 4; ntp++) {
            const int it  = s * 4 + ntp;
            const int cb  = it & 1;
            const int nb  = cb ^ 1;

            // prefetch W fragments for iteration it+1
            if (it + 1 < 32) {
                const int ni   = it + 1;
                const int ns   = ni >> 2;
                const int nntp = ni & 3;
                const uint32_t noff = (uint32_t)(nntp * 16 * WPAD * 2 + ns * 32);
                ldsm4(bh[nb], whi_base + noff);
                ldsm4(bl[nb], wlo_base + noff);
            }

            float* c00 = acc[0][2 * ntp];
            float* c01 = acc[0][2 * ntp + 1];
            float* c10 = acc[1][2 * ntp];
            float* c11 = acc[1][2 * ntp + 1];

            // term 1: Ahi * Whi   (same-acc distance 4)
            mma16816(c00, ah[0], ah[2], ah[1], ah[3], bh[cb][0], bh[cb][1]);
            mma16816(c01, ah[0], ah[2], ah[1], ah[3], bh[cb][2], bh[cb][3]);
            mma16816(c10, ah[4], ah[6], ah[5], ah[7], bh[cb][0], bh[cb][1]);
            mma16816(c11, ah[4], ah[6], ah[5], ah[7], bh[cb][2], bh[cb][3]);
            // term 2: Alo * Whi
            mma16816(c00, al[0], al[2], al[1], al[3], bh[cb][0], bh[cb][1]);
            mma16816(c01, al[0], al[2], al[1], al[3], bh[cb][2], bh[cb][3]);
            mma16816(c10, al[4], al[6], al[5], al[7], bh[cb][0], bh[cb][1]);
            mma16816(c11, al[4], al[6], al[5], al[7], bh[cb][2], bh[cb][3]);
            // term 3: Ahi * Wlo
            mma16816(c00, ah[0], ah[2], ah[1], ah[3], bl[cb][0], bl[cb][1]);
            mma16816(c01, ah[0], ah[2], ah[1], ah[3], bl[cb][2], bl[cb][3]);
            mma16816(c10, ah[4], ah[6], ah[5], ah[7], bl[cb][0], bl[cb][1]);
            mma16816(c11, ah[4], ah[6], ah[5], ah[7], bl[cb][2], bl[cb][3]);
        }
    }

    // ---- epilogue: add bias, store ----
    const int ncol = 2 * (lane & 3);
    #pragma unroll
    for (int f = 0; f < 2; f++) {
        long long row0 = m0 + warp * 32 + f * 16 + (lane >> 2);
        float* orow0 = out + row0 * 64;
        float* orow1 = orow0 + 8 * 64;
        #pragma unroll
        for (int nt = 0; nt < 8; nt++) {
            float2 bv = *reinterpret_cast<const float2*>(bias + nt * 8 + ncol);
            float2 o0, o1;
            o0.x = acc[f][nt][0] + bv.x;  o0.y = acc[f][nt][1] + bv.y;
            o1.x = acc[f][nt][2] + bv.x;  o1.y = acc[f][nt][3] + bv.y;
            *reinterpret_cast<float2*>(orow0 + nt * 8 + ncol) = o0;
            *reinterpret_cast<float2*>(orow1 + nt * 8 + ncol) = o1;
        }
    }
}

extern "C" void kernel_launch(void* const* d_in, const int* in_sizes, int n_in,
                              void* d_out, int out_size) {
    const float* ecg = (const float*)d_in[0];
    const float* W   = (const float*)d_in[1];
    const float* b   = (const float*)d_in[2];
    float* out = (float*)d_out;

    const int M = in_sizes[0] / 128;
    const long long xelems = (long long)M * 64;
    const int fillCount = out_size - (int)xelems;

    ecg_tok_mma<<<M / BM, THREADS>>>(ecg, W, b, out, xelems, fillCount);
}

// round 10
// speedup vs baseline: 1.0535x; 1.0535x over previous
#include <cuda_runtime.h>
#include <cuda_fp16.h>
#include <cstdint>

// out[m][d] = sum_k ecg[m*128+k] * W[d*128+k] + b[d],  M=196608, K=128, N=64.
// 2-term fp16 HMMA: D = A16*Whi + A16*Wlo, W = Whi + Wlo (fp16 split),
// A converted once to fp16. Error ~2^-11 ~ 5e-4 (< 1e-3 gate).
// K columns inside each 16-chunk permuted identically on A and W so a lane's
// LDG.128 float4 converts directly into the a0/a2 fragment registers.

#define THREADS 128
#define BM 128
#define WPAD 136   // fp16 per padded W row (272 B rows -> conflict-free ldmatrix)

__device__ __forceinline__ uint32_t s2u(const void* p) {
    uint32_t a;
    asm("{ .reg .u64 t; cvta.to.shared.u64 t, %1; cvt.u32.u64 %0, t; }" : "=r"(a) : "l"(p));
    return a;
}

// pack two floats into f16x2 (round-to-nearest)
__device__ __forceinline__ uint32_t f16x2(float x, float y) {
    uint32_t r;
    asm("cvt.rn.f16x2.f32 %0, %1, %2;" : "=r"(r) : "f"(y), "f"(x));
    return r;
}

// split (x,y) into fp16 hi + fp16 lo (residual)
__device__ __forceinline__ void split2h(float x, float y, uint32_t& hi, uint32_t& lo) {
    hi = f16x2(x, y);
    __half2 h = *reinterpret_cast<__half2*>(&hi);
    float2 hf = __half22float2(h);
    lo = f16x2(x - hf.x, y - hf.y);
}

__device__ __forceinline__ void ldsm4(uint32_t* r, uint32_t addr) {
    asm volatile("ldmatrix.sync.aligned.m8n8.x4.shared.b16 {%0,%1,%2,%3}, [%4];"
                 : "=r"(r[0]), "=r"(r[1]), "=r"(r[2]), "=r"(r[3]) : "r"(addr));
}

__device__ __forceinline__ void mma16816h(float* c,
                                          uint32_t a0, uint32_t a1, uint32_t a2, uint32_t a3,
                                          uint32_t b0, uint32_t b1) {
    asm volatile(
        "mma.sync.aligned.m16n8k16.row.col.f32.f16.f16.f32 "
        "{%0,%1,%2,%3}, {%4,%5,%6,%7}, {%8,%9}, {%0,%1,%2,%3};"
        : "+f"(c[0]), "+f"(c[1]), "+f"(c[2]), "+f"(c[3])
        : "r"(a0), "r"(a1), "r"(a2), "r"(a3), "r"(b0), "r"(b1));
}

__global__ __launch_bounds__(THREADS, 4)
void ecg_tok_mma(const float* __restrict__ ecg,
                 const float* __restrict__ W,
                 const float* __restrict__ bias,
                 float* __restrict__ out,
                 long long xelems, int fillCount) {
    __shared__ __align__(16) uint32_t Whi32[64 * WPAD / 2];
    __shared__ __align__(16) uint32_t Wlo32[64 * WPAD / 2];

    const int tid  = threadIdx.x;
    const int warp = tid >> 5;
    const int lane = tid & 31;
    const long long m0 = (long long)blockIdx.x * BM;

    // ---- folded fill: beat_intervals tail ----
    {
        int fi = blockIdx.x * THREADS + tid;
        if (fi < fillCount) out[xelems + fi] = 128.0f;
    }

    // ---- prologue: load + split W (fp16 hi/lo) with per-16-chunk column perm ----
    // global pair g of a chunk -> slice pair (g>>1) + (g&1)*4 (same perm on A).
    #pragma unroll
    for (int it = 0; it < 16; it++) {
        int idx   = tid + it * THREADS;     // 0..2047
        int n     = idx >> 5;
        int r     = idx & 31;
        int chunk = r >> 2;
        int q     = r & 3;
        float4 v = *reinterpret_cast<const float4*>(W + n * 128 + chunk * 16 + q * 4);
        uint32_t h0, l0, h1, l1;
        split2h(v.x, v.y, h0, l0);
        split2h(v.z, v.w, h1, l1);
        int u = n * (WPAD / 2) + chunk * 8 + q;
        Whi32[u]     = h0;
        Whi32[u + 4] = h1;
        Wlo32[u]     = l0;
        Wlo32[u + 4] = l1;
    }
    __syncthreads();

    // ldmatrix lane addressing
    const int lm_row  = ((lane >> 4) << 3) + (lane & 7);
    const int lm_kofs = ((lane >> 3) & 1) << 4;   // bytes
    const uint32_t lm_term  = (uint32_t)(lm_row * (WPAD * 2) + lm_kofs);
    const uint32_t whi_base = s2u(Whi32) + lm_term;
    const uint32_t wlo_base = s2u(Wlo32) + lm_term;

    // A geometry: warp rows = warp*32 + {0..31}; lane float4 at col 4*(lane&3)
    const int arow = warp * 32 + (lane >> 2);
    const float* abase = ecg + (m0 + arow) * 128 + 4 * (lane & 3);

    float acc[2][8][4];
    #pragma unroll
    for (int f = 0; f < 2; f++)
        #pragma unroll
        for (int nt = 0; nt < 8; nt++)
            #pragma unroll
            for (int j = 0; j < 4; j++) acc[f][nt][j] = 0.0f;

    // A prefetch (1-deep)
    float4 cur[4];
    #pragma unroll
    for (int j = 0; j < 4; j++)
        cur[j] = *reinterpret_cast<const float4*>(abase + j * 8 * 128);

    #pragma unroll
    for (int s = 0; s < 8; s++) {
        // convert current A chunk to fp16 fragments (single cvt per pair)
        uint32_t ah[8];
        #pragma unroll
        for (int j = 0; j < 4; j++) {
            ah[2 * j]     = f16x2(cur[j].x, cur[j].y);
            ah[2 * j + 1] = f16x2(cur[j].z, cur[j].w);
        }

        // prefetch next A chunk
        if (s < 7) {
            #pragma unroll
            for (int j = 0; j < 4; j++)
                cur[j] = *reinterpret_cast<const float4*>(
                    abase + (s + 1) * 16 + j * 8 * 128);
        }

        #pragma unroll
        for (int ntp = 0; ntp < 4; ntp++) {
            const uint32_t off = (uint32_t)(ntp * 16 * WPAD * 2 + s * 32);
            uint32_t bh[4], bl[4];
            ldsm4(bh, whi_base + off);
            ldsm4(bl, wlo_base + off);

            float* c00 = acc[0][2 * ntp];
            float* c01 = acc[0][2 * ntp + 1];
            float* c10 = acc[1][2 * ntp];
            float* c11 = acc[1][2 * ntp + 1];

            // term 1: A16 * Whi   (term-major: same-acc RAW distance 4)
            mma16816h(c00, ah[0], ah[2], ah[1], ah[3], bh[0], bh[1]);
            mma16816h(c01, ah[0], ah[2], ah[1], ah[3], bh[2], bh[3]);
            mma16816h(c10, ah[4], ah[6], ah[5], ah[7], bh[0], bh[1]);
            mma16816h(c11, ah[4], ah[6], ah[5], ah[7], bh[2], bh[3]);
            // term 2: A16 * Wlo
            mma16816h(c00, ah[0], ah[2], ah[1], ah[3], bl[0], bl[1]);
            mma16816h(c01, ah[0], ah[2], ah[1], ah[3], bl[2], bl[3]);
            mma16816h(c10, ah[4], ah[6], ah[5], ah[7], bl[0], bl[1]);
            mma16816h(c11, ah[4], ah[6], ah[5], ah[7], bl[2], bl[3]);
        }
    }

    // ---- epilogue: add bias, store ----
    const int ncol = 2 * (lane & 3);
    #pragma unroll
    for (int f = 0; f < 2; f++) {
        long long row0 = m0 + warp * 32 + f * 16 + (lane >> 2);
        float* orow0 = out + row0 * 64;
        float* orow1 = orow0 + 8 * 64;
        #pragma unroll
        for (int nt = 0; nt < 8; nt++) {
            float2 bv = *reinterpret_cast<const float2*>(bias + nt * 8 + ncol);
            float2 o0, o1;
            o0.x = acc[f][nt][0] + bv.x;  o0.y = acc[f][nt][1] + bv.y;
            o1.x = acc[f][nt][2] + bv.x;  o1.y = acc[f][nt][3] + bv.y;
            *reinterpret_cast<float2*>(orow0 + nt * 8 + ncol) = o0;
            *reinterpret_cast<float2*>(orow1 + nt * 8 + ncol) = o1;
        }
    }
}

extern "C" void kernel_launch(void* const* d_in, const int* in_sizes, int n_in,
                              void* d_out, int out_size) {
    const float* ecg = (const float*)d_in[0];
    const float* W   = (const float*)d_in[1];
    const float* b   = (const float*)d_in[2];
    float* out = (float*)d_out;

    const int M = in_sizes[0] / 128;
    const long long xelems = (long long)M * 64;
    const int fillCount = out_size - (int)xelems;

    ecg_tok_mma<<<M / BM, THREADS>>>(ecg, W, b, out, xelems, fillCount);
}